// round 10
// baseline (speedup 1.0000x reference)
#include <cuda_runtime.h>
#include <cstdint>
#include <cstddef>

#define C_DIM 256
#define H_DIM 96
#define W_DIM 96
#define TW 24
#define TH 8
#define NPAIR 3
#define RAD 4
#define CC 8
#define NSTAGE (C_DIM / CC)                  // 32
#define S1_STRIDE 40
#define S2_STRIDE 40
#define S2_ROWS (TH + 8)                     // 16
#define S1_WORDS (CC * TH * S1_STRIDE)       // 2560
#define S2_WORDS (CC * S2_ROWS * S2_STRIDE)  // 5120
#define STAGE_WORDS (S1_WORDS + S2_WORDS)    // 7680
#define STAGE_BYTES (STAGE_WORDS * 4)        // 30720
#define NBUF 2
#define NTHREADS 288
#define CADV (CC * H_DIM * W_DIM)

typedef unsigned long long u64;

union F2U { float2 f2; u64 u; };

__device__ __forceinline__ void fma2(u64 &d, u64 a, u64 b) {
    asm("fma.rn.f32x2 %0, %1, %2, %0;" : "+l"(d) : "l"(a), "l"(b));
}
__device__ __forceinline__ void cp16(uint32_t s, const float* g, uint32_t vbit) {
    int sz = vbit ? 16 : 0;
    asm volatile("cp.async.cg.shared.global [%0], [%1], 16, %2;\n"
                 :: "r"(s), "l"(g), "r"(sz));
}

__global__ __launch_bounds__(NTHREADS, 3)
void corr_kernel(const float* __restrict__ in1, const float* __restrict__ in2,
                 float* __restrict__ out) {
    extern __shared__ float smem[];
    const int tid = threadIdx.x;
    const int w0 = blockIdx.x * TW;
    const int h0 = blockIdx.y * TH;
    const int b  = blockIdx.z;

    const int ph   = tid >> 5;          // warp id = displacement row 0..8
    const int lane = tid & 31;
    const int pc   = lane & 3;          // 6-px block 0..3
    const int r    = lane >> 2;         // tile row 0..7
    const int x0   = pc * 6;

    // ---- hoisted load addressing ----
    // in1: threads 0..191 -> 8 floats (2 chunks) of one tile row
    // in2: threads 0..255 -> 16 floats (4 chunks) = half of one 32-float halo row
    const bool l1ok = (tid < 192);
    const bool l2ok = (tid < 256);
    const float* p1 = in1;
    const float* p2 = in2;
    uint32_t d1 = 0, d2 = 0, mask = 0;
    if (l1ok) {
        const int c1   = tid / 24;            // 0..7
        const int rem  = tid % 24;
        const int row1 = rem / 3;             // 0..7
        const int seg  = rem % 3;             // 0..2 (8 floats each)
        p1 = in1 + (((size_t)(b * C_DIM + c1) * H_DIM + (h0 + row1)) * W_DIM + w0 + seg * 8);
        d1 = (uint32_t)(((c1 * TH + row1) * S1_STRIDE + seg * 8) * 4);
    }
    if (l2ok) {
        const int c2   = tid >> 5;            // 0..7
        const int row2 = (tid & 31) >> 1;     // 0..15
        const int half = tid & 1;
        const int h2   = h0 + row2 - RAD;
        const int wst  = w0 - RAD + half * 16;
        const bool hv  = (h2 >= 0) && (h2 < H_DIM);
#pragma unroll
        for (int j = 0; j < 4; j++) {
            int w2 = wst + j * 4;
            if (hv && w2 >= 0 && w2 + 4 <= W_DIM) mask |= (1u << j);
        }
        p2 = in2 + (((size_t)(b * C_DIM + c2) * H_DIM + (hv ? h2 : 0)) * W_DIM + wst);
        d2 = (uint32_t)((S1_WORDS + (c2 * S2_ROWS + row2) * S2_STRIDE + half * 16) * 4);
    }

    u64 accE[NPAIR][5];
    float accO[NPAIR][4][2];
#pragma unroll
    for (int k = 0; k < NPAIR; k++) {
#pragma unroll
        for (int d = 0; d < 5; d++) accE[k][d] = 0ull;
#pragma unroll
        for (int d = 0; d < 4; d++) { accO[k][d][0] = 0.f; accO[k][d][1] = 0.f; }
    }

    const uint32_t sb0 = (uint32_t)__cvta_generic_to_shared(smem);

    auto load_stage = [&](int buf) {
        const uint32_t sbase = sb0 + (uint32_t)(buf * STAGE_BYTES);
        if (l1ok) {
            cp16(sbase + d1,      p1,     1u);
            cp16(sbase + d1 + 16, p1 + 4, 1u);
            p1 += CADV;
        }
        if (l2ok) {
#pragma unroll
            for (int j = 0; j < 4; j++)
                cp16(sbase + d2 + j * 16, p2 + j * 4, (mask >> j) & 1u);
            p2 += CADV;
        }
        asm volatile("cp.async.commit_group;\n");
    };

    load_stage(0);

    for (int s = 0; s < NSTAGE; s++) {
        asm volatile("cp.async.wait_group 0;\n");
        __syncthreads();
        if (s + 1 < NSTAGE) load_stage((s + 1) & 1);

        const float* s1p = smem + (s & 1) * STAGE_WORDS;
        const float* s2p = s1p + S1_WORDS;
#pragma unroll
        for (int cc = 0; cc < CC; cc++) {
            // in1: 3 aligned pairs (LDS.64, conflict-free: 40r+6pc pattern)
            const float2* v1row = (const float2*)(s1p + (cc * TH + r) * S1_STRIDE + x0);
            F2U v1[NPAIR];
#pragma unroll
            for (int q = 0; q < NPAIR; q++) v1[q].f2 = v1row[q];

            // in2: 14-float span as 7 aligned pairs
            const float2* v2row = (const float2*)(s2p + (cc * S2_ROWS + (r + ph)) * S2_STRIDE + x0);
            F2U v2[7];
#pragma unroll
            for (int q = 0; q < 7; q++) v2[q].f2 = v2row[q];

            // even dw: packed FMA on aligned pairs
#pragma unroll
            for (int k = 0; k < NPAIR; k++)
#pragma unroll
                for (int dh = 0; dh < 5; dh++)
                    fma2(accE[k][dh], v1[k].u, v2[k + dh].u);

            // odd dw: scalar FMAs on named halves
#pragma unroll
            for (int k = 0; k < NPAIR; k++)
#pragma unroll
                for (int dh = 0; dh < 4; dh++) {
                    accO[k][dh][0] = __fmaf_rn(v1[k].f2.x, v2[k + dh].f2.y, accO[k][dh][0]);
                    accO[k][dh][1] = __fmaf_rn(v1[k].f2.y, v2[k + dh + 1].f2.x, accO[k][dh][1]);
                }
        }
    }

    // epilogue
    const size_t plane = (size_t)H_DIM * W_DIM;
    float* op = out + (size_t)(b * 81 + ph * 9) * plane +
                (size_t)(h0 + r) * W_DIM + (w0 + x0);
#pragma unroll
    for (int dh = 0; dh < 5; dh++) {
        u64* orow = (u64*)(op + (size_t)(2 * dh) * plane);
#pragma unroll
        for (int k = 0; k < NPAIR; k++) orow[k] = accE[k][dh];
    }
#pragma unroll
    for (int dh = 0; dh < 4; dh++) {
        float* orow = op + (size_t)(2 * dh + 1) * plane;
#pragma unroll
        for (int k = 0; k < NPAIR; k++) {
            F2U t; t.f2.x = accO[k][dh][0]; t.f2.y = accO[k][dh][1];
            *(u64*)(orow + 2 * k) = t.u;
        }
    }
}

extern "C" void kernel_launch(void* const* d_in, const int* in_sizes, int n_in,
                              void* d_out, int out_size) {
    const float* in1 = (const float*)d_in[0];
    const float* in2 = (const float*)d_in[1];
    float* out = (float*)d_out;
    int Bn = in_sizes[0] / (C_DIM * H_DIM * W_DIM);
    size_t smem_bytes = (size_t)NBUF * STAGE_BYTES;  // 61440
    cudaFuncSetAttribute(corr_kernel, cudaFuncAttributeMaxDynamicSharedMemorySize,
                         (int)smem_bytes);
    dim3 grid(W_DIM / TW, H_DIM / TH, Bn);
    corr_kernel<<<grid, NTHREADS, smem_bytes>>>(in1, in2, out);
}

// round 12
// speedup vs baseline: 1.4723x; 1.4723x over previous
#include <cuda_runtime.h>
#include <cstdint>
#include <cstddef>

#define C_DIM 256
#define H_DIM 96
#define W_DIM 96
#define TW 16
#define TH 8
#define NPAIR 2
#define RAD 4
#define CC 8
#define NSTAGE (C_DIM / CC)                  // 32
#define S1_ROW 24                            // words per in1 row slot (16 data + swizzle)
#define S1_CH  (TH * S1_ROW)                 // 192
#define S1_WORDS (CC * S1_CH)                // 1536
#define S2_ROWS (TH + 8)                     // 16
#define S2_ROW 40                            // words per in2 row slot (24 data + swizzle)
#define S2_CH  (S2_ROWS * S2_ROW)            // 640
#define S2_WORDS (CC * S2_CH)                // 5120
#define STAGE_WORDS (S1_WORDS + S2_WORDS)    // 6656
#define STAGE_BYTES (STAGE_WORDS * 4)        // 26624
#define NBUF 2
#define NTHREADS 288
#define CADV (CC * H_DIM * W_DIM)            // channel advance per stage (floats)

typedef unsigned long long u64;

union F2U { float2 f2; u64 u; };

__device__ __forceinline__ void fma2(u64 &d, u64 a, u64 b) {
    asm("fma.rn.f32x2 %0, %1, %2, %0;" : "+l"(d) : "l"(a), "l"(b));
}
__device__ __forceinline__ void cp8(uint32_t s, const float* g, uint32_t vbit) {
    int sz = vbit ? 8 : 0;
    asm volatile("cp.async.ca.shared.global [%0], [%1], 8, %2;\n"
                 :: "r"(s), "l"(g), "r"(sz));
}

// row swizzles (8B-granular shifts), derived for full 32-bank partitions:
// in1 bases 24r+2(r&1) -> {0,26,16,10} per phase; in2 bases 8y+10(y&1) -> {0,18,16,2}
__device__ __forceinline__ int swz1(int r) { return 2 * (r & 1); }
__device__ __forceinline__ int swz2(int y) { return 10 * (y & 1); }

__global__ __launch_bounds__(NTHREADS, 3)
void corr_kernel(const float* __restrict__ in1, const float* __restrict__ in2,
                 float* __restrict__ out) {
    extern __shared__ float smem[];
    const int tid = threadIdx.x;
    const int w0 = blockIdx.x * TW;
    const int h0 = blockIdx.y * TH;
    const int b  = blockIdx.z;

    const int ph   = tid >> 5;          // warp id = displacement row 0..8
    const int lane = tid & 31;
    const int pc   = lane & 3;          // 4-px block 0..3
    const int r    = lane >> 2;         // tile row 0..7
    const int x0   = pc * 4;

    // ---- hoisted load addressing (256 loader threads, 8x 8B cp.async each) ----
    const bool loader = (tid < 256);
    const float* p1 = in1;
    const float* p2 = in2;
    uint32_t d1 = 0, d2 = 0, mask = 0;
    int adj = 0;
    if (loader) {
        // in1: 4 consecutive floats (2 chunks) of one row
        const int c1   = tid >> 5;            // 0..7
        const int rem  = tid & 31;
        const int row1 = rem >> 2;            // 0..7
        const int xq   = (rem & 3) * 4;       // 0,4,8,12
        p1 = in1 + (((size_t)(b * C_DIM + c1) * H_DIM + (h0 + row1)) * W_DIM + w0 + xq);
        d1 = (uint32_t)((c1 * S1_CH + row1 * S1_ROW + swz1(row1) + xq) * 4);

        // in2: 12 floats (6 chunks) = half of one 24-float halo row
        const int c2   = tid >> 5;            // 0..7
        const int rid  = tid & 31;
        const int y    = rid >> 1;            // 0..15
        const int half = rid & 1;
        const int xf   = half * 12;
        const int h2   = h0 + y - RAD;
        const int wst  = w0 - RAD + xf;       // global column of word xf (even, >= -4, <= 88)
        const bool hv  = (h2 >= 0) && (h2 < H_DIM);
#pragma unroll
        for (int j = 0; j < 6; j++) {
            int wg = wst + 2 * j;             // even; chunk covers wg, wg+1
            if (hv && wg >= 0 && wg < W_DIM) mask |= (1u << j);
        }
        const int wc = (wst < 0) ? 0 : wst;   // safe base column
        adj = wst - wc;                       // 0 or -4
        p2 = in2 + (((size_t)(b * C_DIM + c2) * H_DIM + (hv ? h2 : 0)) * W_DIM + wc);
        d2 = (uint32_t)((S1_WORDS + c2 * S2_CH + y * S2_ROW + swz2(y) + xf) * 4);
    }

    u64 accE[NPAIR][5];
    float accO[NPAIR][4][2];
#pragma unroll
    for (int k = 0; k < NPAIR; k++) {
#pragma unroll
        for (int d = 0; d < 5; d++) accE[k][d] = 0ull;
#pragma unroll
        for (int d = 0; d < 4; d++) { accO[k][d][0] = 0.f; accO[k][d][1] = 0.f; }
    }

    const uint32_t sb0 = (uint32_t)__cvta_generic_to_shared(smem);

    auto load_stage = [&](int buf) {
        if (loader) {
            const uint32_t sbase = sb0 + (uint32_t)(buf * STAGE_BYTES);
            cp8(sbase + d1,     p1,     1u);
            cp8(sbase + d1 + 8, p1 + 2, 1u);
#pragma unroll
            for (int j = 0; j < 6; j++) {
                uint32_t v = (mask >> j) & 1u;
                const float* src = p2 + (v ? (2 * j + adj) : 0);
                cp8(sbase + d2 + j * 8, src, v);
            }
            p1 += CADV;
            p2 += CADV;
        }
        asm volatile("cp.async.commit_group;\n");
    };

    load_stage(0);

    // per-thread compute offsets (words)
    const int o1 = r * S1_ROW + swz1(r) + x0;
    const int y0 = r + ph;
    const int o2 = S1_WORDS + y0 * S2_ROW + swz2(y0) + x0;

    for (int s = 0; s < NSTAGE; s++) {
        asm volatile("cp.async.wait_group 0;\n");
        __syncthreads();
        if (s + 1 < NSTAGE) load_stage((s + 1) & 1);

        const float* sp = smem + (s & 1) * STAGE_WORDS;
#pragma unroll
        for (int cc = 0; cc < CC; cc++) {
            // in1: 2 aligned pairs (LDS.64, swizzle-verified conflict-free)
            const float2* v1row = (const float2*)(sp + cc * S1_CH + o1);
            F2U v1[NPAIR];
#pragma unroll
            for (int q = 0; q < NPAIR; q++) v1[q].f2 = v1row[q];

            // in2: 12-float span as 6 aligned pairs (swizzle-verified conflict-free)
            const float2* v2row = (const float2*)(sp + cc * S2_CH + o2);
            F2U v2[6];
#pragma unroll
            for (int q = 0; q < 6; q++) v2[q].f2 = v2row[q];

            // even dw: packed FMA
#pragma unroll
            for (int k = 0; k < NPAIR; k++)
#pragma unroll
                for (int dh = 0; dh < 5; dh++)
                    fma2(accE[k][dh], v1[k].u, v2[k + dh].u);

            // odd dw: scalar FMAs on named halves
#pragma unroll
            for (int k = 0; k < NPAIR; k++)
#pragma unroll
                for (int dh = 0; dh < 4; dh++) {
                    accO[k][dh][0] = __fmaf_rn(v1[k].f2.x, v2[k + dh].f2.y, accO[k][dh][0]);
                    accO[k][dh][1] = __fmaf_rn(v1[k].f2.y, v2[k + dh + 1].f2.x, accO[k][dh][1]);
                }
        }
    }

    // epilogue
    const size_t plane = (size_t)H_DIM * W_DIM;
    float* op = out + (size_t)(b * 81 + ph * 9) * plane +
                (size_t)(h0 + r) * W_DIM + (w0 + x0);
#pragma unroll
    for (int dh = 0; dh < 5; dh++) {
        u64* orow = (u64*)(op + (size_t)(2 * dh) * plane);
#pragma unroll
        for (int k = 0; k < NPAIR; k++) orow[k] = accE[k][dh];
    }
#pragma unroll
    for (int dh = 0; dh < 4; dh++) {
        float* orow = op + (size_t)(2 * dh + 1) * plane;
#pragma unroll
        for (int k = 0; k < NPAIR; k++) {
            F2U t; t.f2.x = accO[k][dh][0]; t.f2.y = accO[k][dh][1];
            *(u64*)(orow + 2 * k) = t.u;
        }
    }
}

extern "C" void kernel_launch(void* const* d_in, const int* in_sizes, int n_in,
                              void* d_out, int out_size) {
    const float* in1 = (const float*)d_in[0];
    const float* in2 = (const float*)d_in[1];
    float* out = (float*)d_out;
    int Bn = in_sizes[0] / (C_DIM * H_DIM * W_DIM);
    size_t smem_bytes = (size_t)NBUF * STAGE_BYTES;  // 53248
    cudaFuncSetAttribute(corr_kernel, cudaFuncAttributeMaxDynamicSharedMemorySize,
                         (int)smem_bytes);
    dim3 grid(W_DIM / TW, H_DIM / TH, Bn);
    corr_kernel<<<grid, NTHREADS, smem_bytes>>>(in1, in2, out);
}

// round 13
// speedup vs baseline: 2.0391x; 1.3850x over previous
#include <cuda_runtime.h>
#include <cstdint>
#include <cstddef>

#define C_DIM 256
#define H_DIM 96
#define W_DIM 96
#define TW 16
#define TH 8
#define NPAIR 2
#define RAD 4
#define CC 8
#define NSTAGE (C_DIM / CC)                  // 32
#define S1_ROW 16                            // in1 row slot (16 data words, stride 16 ≡ 16 mod 32)
#define S1_CH  (TH * S1_ROW)                 // 128
#define S1_WORDS (CC * S1_CH)                // 1024
#define S2_ROWS (TH + 8)                     // 16
#define S2_ROW 48                            // in2 row slot (24 data words, stride 48 ≡ 16 mod 32)
#define S2_CH  (S2_ROWS * S2_ROW)            // 768
#define S2_WORDS (CC * S2_CH)                // 6144
#define STAGE_WORDS (S1_WORDS + S2_WORDS)    // 7168
#define STAGE_BYTES (STAGE_WORDS * 4)        // 28672
#define NBUF 2
#define NTHREADS 288
#define CADV (CC * H_DIM * W_DIM)            // channel advance per stage (floats)

typedef unsigned long long u64;

union F2U { float2 f2; u64 u; };

__device__ __forceinline__ void fma2(u64 &d, u64 a, u64 b) {
    asm("fma.rn.f32x2 %0, %1, %2, %0;" : "+l"(d) : "l"(a), "l"(b));
}
__device__ __forceinline__ void cp16(uint32_t s, const float* g, uint32_t vbit) {
    int sz = vbit ? 16 : 0;
    asm volatile("cp.async.cg.shared.global [%0], [%1], 16, %2;\n"
                 :: "r"(s), "l"(g), "r"(sz));
}

__global__ __launch_bounds__(NTHREADS, 3)
void corr_kernel(const float* __restrict__ in1, const float* __restrict__ in2,
                 float* __restrict__ out) {
    extern __shared__ float smem[];
    const int tid = threadIdx.x;
    const int w0 = blockIdx.x * TW;
    const int h0 = blockIdx.y * TH;
    const int b  = blockIdx.z;

    const int ph   = tid >> 5;          // warp id = displacement row 0..8
    const int lane = tid & 31;
    const int pc   = lane & 3;          // 4-px block 0..3
    const int r    = lane >> 2;         // tile row 0..7
    const int x0   = pc * 4;

    // ---- hoisted load addressing (256 loader threads, 4x 16B cp.async each) ----
    const bool loader = (tid < 256);
    const float* p1 = in1;
    const float* p2 = in2;
    uint32_t d1 = 0, d2 = 0, mask = 0;
    int adj = 0;
    if (loader) {
        // in1: one 16B chunk (4 floats) of one row
        const int c1   = tid >> 5;            // 0..7
        const int rem  = tid & 31;
        const int row1 = rem >> 2;            // 0..7
        const int q    = rem & 3;             // 0..3
        p1 = in1 + (((size_t)(b * C_DIM + c1) * H_DIM + (h0 + row1)) * W_DIM + w0 + q * 4);
        d1 = (uint32_t)((c1 * S1_CH + row1 * S1_ROW + q * 4) * 4);

        // in2: 3 x 16B chunks = half of one 24-float halo row
        const int c2   = tid >> 5;            // 0..7
        const int rid  = tid & 31;
        const int y    = rid >> 1;            // 0..15
        const int half = rid & 1;
        const int h2   = h0 + y - RAD;
        const int col0 = w0 - RAD + half * 12;   // 4-aligned global start column
        const bool hv  = (h2 >= 0) && (h2 < H_DIM);
#pragma unroll
        for (int j = 0; j < 3; j++) {
            int cg = col0 + 4 * j;            // chunk covers [cg, cg+3]; all-or-nothing
            if (hv && cg >= 0 && cg + 4 <= W_DIM) mask |= (1u << j);
        }
        const int wc = (col0 < 0) ? 0 : (col0 > W_DIM - 4 ? W_DIM - 4 : col0);
        adj = col0 - wc;
        p2 = in2 + (((size_t)(b * C_DIM + c2) * H_DIM + (hv ? h2 : 0)) * W_DIM + wc);
        d2 = (uint32_t)((S1_WORDS + c2 * S2_CH + y * S2_ROW + half * 12) * 4);
    }

    u64 accE[NPAIR][5];
    float accO[NPAIR][4][2];
#pragma unroll
    for (int k = 0; k < NPAIR; k++) {
#pragma unroll
        for (int d = 0; d < 5; d++) accE[k][d] = 0ull;
#pragma unroll
        for (int d = 0; d < 4; d++) { accO[k][d][0] = 0.f; accO[k][d][1] = 0.f; }
    }

    const uint32_t sb0 = (uint32_t)__cvta_generic_to_shared(smem);

    auto load_stage = [&](int buf) {
        if (loader) {
            const uint32_t sbase = sb0 + (uint32_t)(buf * STAGE_BYTES);
            cp16(sbase + d1, p1, 1u);
#pragma unroll
            for (int j = 0; j < 3; j++) {
                uint32_t v = (mask >> j) & 1u;
                const float* src = p2 + (v ? (4 * j + adj) : 0);
                cp16(sbase + d2 + j * 16, src, v);
            }
            p1 += CADV;
            p2 += CADV;
        }
        asm volatile("cp.async.commit_group;\n");
    };

    load_stage(0);

    // per-thread compute offsets (words)
    const int o1 = r * S1_ROW + x0;
    const int y0 = r + ph;
    const int o2 = S1_WORDS + y0 * S2_ROW + x0;

    for (int s = 0; s < NSTAGE; s++) {
        asm volatile("cp.async.wait_group 0;\n");
        __syncthreads();
        if (s + 1 < NSTAGE) load_stage((s + 1) & 1);

        const float* sp = smem + (s & 1) * STAGE_WORDS;
#pragma unroll
        for (int cc = 0; cc < CC; cc++) {
            // in1: 4 px via one LDS.128 (conflict-free: starts 16r+4pc)
            float4 t1 = *(const float4*)(sp + cc * S1_CH + o1);
            F2U v1[NPAIR];
            v1[0].f2 = make_float2(t1.x, t1.y);
            v1[1].f2 = make_float2(t1.z, t1.w);

            // in2: 12-float span via 3 LDS.128 (conflict-free: stride 48 ≡ 16 mod 32)
            const float4* v2row = (const float4*)(sp + cc * S2_CH + o2);
            F2U v2[6];
#pragma unroll
            for (int q = 0; q < 3; q++) {
                float4 t = v2row[q];
                v2[2 * q].f2     = make_float2(t.x, t.y);
                v2[2 * q + 1].f2 = make_float2(t.z, t.w);
            }

            // even dw: packed FMA
#pragma unroll
            for (int k = 0; k < NPAIR; k++)
#pragma unroll
                for (int dh = 0; dh < 5; dh++)
                    fma2(accE[k][dh], v1[k].u, v2[k + dh].u);

            // odd dw: scalar FMAs on named halves
#pragma unroll
            for (int k = 0; k < NPAIR; k++)
#pragma unroll
                for (int dh = 0; dh < 4; dh++) {
                    accO[k][dh][0] = __fmaf_rn(v1[k].f2.x, v2[k + dh].f2.y, accO[k][dh][0]);
                    accO[k][dh][1] = __fmaf_rn(v1[k].f2.y, v2[k + dh + 1].f2.x, accO[k][dh][1]);
                }
        }
    }

    // epilogue
    const size_t plane = (size_t)H_DIM * W_DIM;
    float* op = out + (size_t)(b * 81 + ph * 9) * plane +
                (size_t)(h0 + r) * W_DIM + (w0 + x0);
#pragma unroll
    for (int dh = 0; dh < 5; dh++) {
        u64* orow = (u64*)(op + (size_t)(2 * dh) * plane);
#pragma unroll
        for (int k = 0; k < NPAIR; k++) orow[k] = accE[k][dh];
    }
#pragma unroll
    for (int dh = 0; dh < 4; dh++) {
        float* orow = op + (size_t)(2 * dh + 1) * plane;
#pragma unroll
        for (int k = 0; k < NPAIR; k++) {
            F2U t; t.f2.x = accO[k][dh][0]; t.f2.y = accO[k][dh][1];
            *(u64*)(orow + 2 * k) = t.u;
        }
    }
}

extern "C" void kernel_launch(void* const* d_in, const int* in_sizes, int n_in,
                              void* d_out, int out_size) {
    const float* in1 = (const float*)d_in[0];
    const float* in2 = (const float*)d_in[1];
    float* out = (float*)d_out;
    int Bn = in_sizes[0] / (C_DIM * H_DIM * W_DIM);
    size_t smem_bytes = (size_t)NBUF * STAGE_BYTES;  // 57344
    cudaFuncSetAttribute(corr_kernel, cudaFuncAttributeMaxDynamicSharedMemorySize,
                         (int)smem_bytes);
    dim3 grid(W_DIM / TW, H_DIM / TH, Bn);
    corr_kernel<<<grid, NTHREADS, smem_bytes>>>(in1, in2, out);
}